// round 8
// baseline (speedup 1.0000x reference)
#include <cuda_runtime.h>
#include <cuda_fp16.h>
#include <cstdint>

// ---------------- problem constants ----------------
#define M_DIM 512
#define K_DIM 512
#define N_DIM 100000
#define NC    10
#define CAND  16
#define CAP   512
#define THR   0.125f
#define TAU   3e-4f
#define SCALE 64.0f
#define INV_SCALE 0.015625f
#define COS_M  0.87758256189037276f
#define SIN_M  0.47942553860420301f
#define SINM_M 0.23971276930210150f
#define EPSN  1e-12f
#define NEG_INF (-3.402823466e38f)

#define LOGITS_SZ ((size_t)M_DIM * N_DIM)
#define INTRA_OFF LOGITS_SZ
#define HARD_OFF  (LOGITS_SZ + M_DIM)

// ---------------- device scratch ----------------
__device__ __half g_xh[M_DIM * K_DIM];
__device__ int    g_y[M_DIM];
__device__ int    g_cnt[M_DIM];
__device__ float  g_cval[M_DIM * CAP];
__device__ int    g_ccol[M_DIM * CAP];

// ---------------- PTX helpers ----------------
__device__ __forceinline__ uint32_t smem_u32(const void* p) {
    uint32_t a;
    asm("{ .reg .u64 t; cvta.to.shared.u64 t, %1; cvt.u32.u64 %0, t; }" : "=r"(a) : "l"(p));
    return a;
}
__device__ __forceinline__ void cpa16(uint32_t s, const void* g) {
    asm volatile("cp.async.cg.shared.global [%0], [%1], 16;" :: "r"(s), "l"(g));
}
#define CP_COMMIT() asm volatile("cp.async.commit_group;" ::: "memory")
#define CP_WAIT1()  asm volatile("cp.async.wait_group 1;" ::: "memory")

__device__ __forceinline__ void sts64(uint32_t a, uint32_t r0, uint32_t r1) {
    asm volatile("st.shared.v2.b32 [%0], {%1,%2};" :: "r"(a), "r"(r0), "r"(r1));
}
__device__ __forceinline__ void ldsm4(uint32_t* r, uint32_t a) {
    asm volatile("ldmatrix.sync.aligned.m8n8.x4.shared.b16 {%0,%1,%2,%3}, [%4];"
        : "=r"(r[0]), "=r"(r[1]), "=r"(r[2]), "=r"(r[3]) : "r"(a));
}
__device__ __forceinline__ void ldsm4t(uint32_t* r, uint32_t a) {
    asm volatile("ldmatrix.sync.aligned.m8n8.x4.trans.shared.b16 {%0,%1,%2,%3}, [%4];"
        : "=r"(r[0]), "=r"(r[1]), "=r"(r[2]), "=r"(r[3]) : "r"(a));
}
__device__ __forceinline__ void mma16816(float* c, const uint32_t* a, const uint32_t* b) {
    asm volatile("mma.sync.aligned.m16n8k16.row.col.f32.f16.f16.f32 "
        "{%0,%1,%2,%3}, {%4,%5,%6,%7}, {%8,%9}, {%0,%1,%2,%3};"
        : "+f"(c[0]), "+f"(c[1]), "+f"(c[2]), "+f"(c[3])
        : "r"(a[0]), "r"(a[1]), "r"(a[2]), "r"(a[3]), "r"(b[0]), "r"(b[1]));
}

// ---- double-single (compensated fp32) accumulation ----
struct DS { float hi, lo; };
__device__ __forceinline__ void ds_add(DS& a, float p) {
    float s = a.hi + p;
    float v = s - a.hi;
    float e = (a.hi - (s - v)) + (p - v);
    a.hi = s;
    a.lo += e;
}
__device__ __forceinline__ void ds_fma(DS& a, float x, float w) {
    float p  = x * w;
    float pe = fmaf(x, w, -p);
    ds_add(a, p);
    a.lo += pe;
}
__device__ __forceinline__ void ds_reduce(DS& a) {
#pragma unroll
    for (int o = 16; o; o >>= 1) {
        float oh = __shfl_xor_sync(0xffffffffu, a.hi, o);
        float ol = __shfl_xor_sync(0xffffffffu, a.lo, o);
        float s = a.hi + oh;
        float v = s - a.hi;
        float e = (a.hi - (s - v)) + (oh - v);
        a.hi = s;
        a.lo += ol + e;
    }
}

// ---------------- kernel 0: decode y + zero counters ----------
__global__ void ydecode_kernel(const int* __restrict__ y32) {
    __shared__ int zeros;
    int t = threadIdx.x;
    if (t == 0) zeros = 0;
    __syncthreads();
    if (t < 256) {
        if (y32[2 * t + 1] == 0) atomicAdd(&zeros, 1);
    }
    __syncthreads();
    bool is64 = (zeros > 8);
    g_y[t] = is64 ? y32[2 * t] : y32[t];
    g_cnt[t] = 0;
}

// ---------------- kernel 1: row-normalize x -> fp16 ----------------
__global__ void xnorm_kernel(const float* __restrict__ x) {
    int gw   = (blockIdx.x * blockDim.x + threadIdx.x) >> 5;
    int lane = threadIdx.x & 31;
    if (gw >= M_DIM) return;
    const float* xr = x + (size_t)gw * K_DIM;
    float v[16];
    float s = 0.f;
#pragma unroll
    for (int i = 0; i < 16; i++) {
        v[i] = xr[lane + 32 * i];
        s = fmaf(v[i], v[i], s);
    }
#pragma unroll
    for (int o = 16; o; o >>= 1) s += __shfl_xor_sync(0xffffffffu, s, o);
    float inv = 1.0f / fmaxf(sqrtf(s), EPSN);
#pragma unroll
    for (int i = 0; i < 16; i++)
        g_xh[(size_t)gw * K_DIM + lane + 32 * i] = __float2half(v[i] * inv);
}

// ---------------- kernel 2: fused GEMM (W fp32 -> fp16 in-kernel) ----------
#define OFF_A    0                 // 3 x 16KB A stages
#define OFF_B    49152             // 2 x 16KB fp16 B stages
#define OFF_RED  81920             // 8 x 128 floats colsumsq
#define OFF_CINV 86016             // 128 floats
#define SMEM_TOTAL 86528

__global__ __launch_bounds__(256, 2)
void arcface_gemm_kernel(const float* __restrict__ W, float* __restrict__ out) {
    extern __shared__ char smem[];
    const uint32_t sb = smem_u32(smem);
    const int tid  = threadIdx.x;
    const int lane = tid & 31;
    const int w    = tid >> 5;
    const int wm   = w >> 2;
    const int wn   = w & 3;
    const int m0   = blockIdx.x * 128;
    const int n0   = blockIdx.y * 128;
    const bool fullt = (n0 + 128 <= N_DIM);

    float acc[4][4][4];
#pragma unroll
    for (int a = 0; a < 4; a++)
#pragma unroll
        for (int b = 0; b < 4; b++)
#pragma unroll
            for (int c = 0; c < 4; c++) acc[a][b][c] = 0.f;

    auto Aaddr = [&](int s, int m, int c) -> uint32_t {
        return sb + OFF_A + s * 16384 + m * 128 + (((c ^ (m & 7)) & 7) << 4);
    };
    auto Baddr = [&](int s, int k, int c16) -> uint32_t {
        return sb + OFF_B + s * 16384 + k * 256 + (((c16 ^ (k & 7)) & 15) << 4);
    };

    auto stage_a = [&](int s, int kc) {
        const int k0 = kc * 64;
#pragma unroll
        for (int j = 0; j < 4; j++) {
            int l = tid + j * 256;
            int m = l >> 3, c = l & 7;
            cpa16(Aaddr(s, m, c), g_xh + (size_t)(m0 + m) * K_DIM + k0 + c * 8);
        }
    };

    const int bc   = tid & 31;
    const int bkst = tid >> 5;
    const int bn   = n0 + bc * 4;
    float4 bregs[8];
    float cs[4] = {0.f, 0.f, 0.f, 0.f};

    auto ldB = [&](int kc) {
        const int k0 = kc * 64;
        if (fullt) {
#pragma unroll
            for (int j = 0; j < 8; j++) {
                int k = bkst + 8 * j;
                bregs[j] = *reinterpret_cast<const float4*>(
                    W + (size_t)(k0 + k) * N_DIM + bn);
            }
        } else {
#pragma unroll
            for (int j = 0; j < 8; j++) {
                int k = bkst + 8 * j;
                const float* wr = W + (size_t)(k0 + k) * N_DIM;
                float4 v;
                v.x = (bn + 0 < N_DIM) ? wr[bn + 0] : 0.f;
                v.y = (bn + 1 < N_DIM) ? wr[bn + 1] : 0.f;
                v.z = (bn + 2 < N_DIM) ? wr[bn + 2] : 0.f;
                v.w = (bn + 3 < N_DIM) ? wr[bn + 3] : 0.f;
                bregs[j] = v;
            }
        }
    };
    auto cvtB = [&](int s) {
#pragma unroll
        for (int j = 0; j < 8; j++) {
            float4 v = bregs[j];
            cs[0] = fmaf(v.x, v.x, cs[0]);
            cs[1] = fmaf(v.y, v.y, cs[1]);
            cs[2] = fmaf(v.z, v.z, cs[2]);
            cs[3] = fmaf(v.w, v.w, cs[3]);
            __half2 h0 = __floats2half2_rn(v.x, v.y);
            __half2 h1 = __floats2half2_rn(v.z, v.w);
            int k = bkst + 8 * j;
            uint32_t a = Baddr(s, k, bc >> 1) + (bc & 1) * 8;
            sts64(a, *reinterpret_cast<uint32_t*>(&h0),
                     *reinterpret_cast<uint32_t*>(&h1));
        }
    };

    const int g  = lane >> 3;
    const int l8 = lane & 7;

    auto compute = [&](int sa, int sbuf) {
#pragma unroll
        for (int kk = 0; kk < 4; kk++) {
            uint32_t af[4][4];
#pragma unroll
            for (int mi = 0; mi < 4; mi++) {
                int ml = wm * 64 + mi * 16 + (g & 1) * 8 + l8;
                int c0 = kk * 2 + (g >> 1);
                ldsm4(af[mi], Aaddr(sa, ml, c0));
            }
            uint32_t bf[2][4];
#pragma unroll
            for (int np = 0; np < 2; np++) {
                int kl = kk * 16 + (g & 1) * 8 + l8;
                int cn = wn * 4 + np * 2 + (g >> 1);
                ldsm4t(bf[np], Baddr(sbuf, kl, cn));
            }
#pragma unroll
            for (int mi = 0; mi < 4; mi++)
#pragma unroll
                for (int ni = 0; ni < 4; ni++)
                    mma16816(acc[mi][ni], af[mi], &bf[ni >> 1][(ni & 1) * 2]);
        }
    };

    ldB(0);
    stage_a(0, 0); CP_COMMIT();
    stage_a(1, 1); CP_COMMIT();
#pragma unroll 1
    for (int kc = 0; kc < 8; kc++) {
        cvtB(kc & 1);
        if (kc + 1 < 8) ldB(kc + 1);
        CP_WAIT1();
        __syncthreads();
        if (kc + 2 < 8) stage_a((kc + 2) % 3, kc + 2);
        CP_COMMIT();
        compute(kc % 3, kc & 1);
    }

    // ---- column norms (deterministic tree reduce over 8 k-stripes) ----
    float* red = reinterpret_cast<float*>(smem + OFF_RED);
    __syncthreads();
#pragma unroll
    for (int jj = 0; jj < 4; jj++) red[bkst * 128 + bc * 4 + jj] = cs[jj];
    __syncthreads();
    float* cinv = reinterpret_cast<float*>(smem + OFF_CINV);
    if (tid < 128) {
        float s = 0.f;
#pragma unroll
        for (int r = 0; r < 8; r++) s += red[r * 128 + tid];
        cinv[tid] = 1.0f / fmaxf(sqrtf(s), EPSN);
    }
    __syncthreads();

    // ---------------- epilogue ----------------
#pragma unroll
    for (int mi = 0; mi < 4; mi++) {
        const int rbase = m0 + wm * 64 + mi * 16 + (lane >> 2);
#pragma unroll
        for (int h = 0; h < 2; h++) {
            const int row = rbase + h * 8;
            const int yr  = g_y[row];
            float* orow = out + (size_t)row * N_DIM;
#pragma unroll
            for (int ni = 0; ni < 4; ni++) {
                const int nl = wn * 32 + ni * 8 + (lane & 3) * 2;
                const int cb = n0 + nl;
                float lg[2];
#pragma unroll
                for (int e = 0; e < 2; e++) {
                    const int col = cb + e;
                    float c = acc[mi][ni][h * 2 + e] * cinv[nl + e];
                    c = fminf(1.f, fmaxf(-1.f, c));
                    float l = SCALE * c;
                    if (col == yr) {
                        float mg;
                        if (c > -COS_M)
                            mg = c * COS_M - sqrtf(fmaxf(0.f, 1.f - c * c)) * SIN_M;
                        else
                            mg = c - SINM_M;
                        l = SCALE * mg;
                        out[INTRA_OFF + row] = c;
                    } else if (c > THR && col < N_DIM) {
                        int slot = atomicAdd(&g_cnt[row], 1);
                        if (slot < CAP) {
                            g_cval[row * CAP + slot] = c;
                            g_ccol[row * CAP + slot] = col;
                        }
                    }
                    lg[e] = l;
                }
                if (fullt) {
                    *reinterpret_cast<float2*>(orow + cb) = make_float2(lg[0], lg[1]);
                } else {
                    if (cb     < N_DIM) orow[cb]     = lg[0];
                    if (cb + 1 < N_DIM) orow[cb + 1] = lg[1];
                }
            }
        }
    }
}

// ---------------- kernel 3: select + SELECTIVE exact refine --------
// Top-16 by fp16-GEMM cosine, exact (DS) recompute only where sorted
// neighbors are closer than TAU (fp16-cosine abs err ~1.4e-5 rms << TAU).
__global__ void refine_kernel(const float* __restrict__ x,
                              const float* __restrict__ W,
                              float* __restrict__ out) {
    const int row  = blockIdx.x;
    const int t    = threadIdx.x;
    const int warp = t >> 5;
    const int lane = t & 31;
    const int yr   = g_y[row];

    __shared__ float svals[CAND];
    __shared__ int   scols[CAND];
    __shared__ int   smask;
    const int cnt = g_cnt[row];

    if (cnt >= CAND && cnt <= CAP) {
        if (warp == 0) {
            float v[CAND];
            int   id[CAND];
#pragma unroll
            for (int j = 0; j < CAND; j++) { v[j] = NEG_INF; id[j] = 0x7fffffff; }
            for (int i = lane; i < cnt; i += 32) {
                float val = g_cval[row * CAP + i];
                int   col = g_ccol[row * CAP + i];
                if (val > v[CAND - 1]) {
                    v[CAND - 1] = val;
                    id[CAND - 1] = col;
#pragma unroll
                    for (int j = CAND - 1; j > 0; --j) {
                        if (v[j] > v[j - 1]) {
                            float tv = v[j]; v[j] = v[j - 1]; v[j - 1] = tv;
                            int ti = id[j]; id[j] = id[j - 1]; id[j - 1] = ti;
                        }
                    }
                }
            }
            int ptr = 0;
            for (int r = 0; r < CAND; ++r) {
                float myv = (ptr < CAND) ? v[ptr] : NEG_INF;
                int   myi = (ptr < CAND) ? id[ptr] : 0x7fffffff;
                float bv = myv;
                int   bi = myi;
#pragma unroll
                for (int o = 16; o; o >>= 1) {
                    float ov = __shfl_xor_sync(0xffffffffu, bv, o);
                    int   oi = __shfl_xor_sync(0xffffffffu, bi, o);
                    if (ov > bv || (ov == bv && oi < bi)) { bv = ov; bi = oi; }
                }
                if (ptr < CAND && bi == myi) ptr++;
                if (lane == 0) { svals[r] = bv; scols[r] = bi; }
            }
        }
        __syncthreads();
        // mark ambiguous: gap to either sorted neighbor < TAU
        if (t == 0) {
            int mask = 0;
            for (int r = 0; r < CAND; ++r) {
                bool m = false;
                if (r > 0        && svals[r - 1] - svals[r] < TAU) m = true;
                if (r < CAND - 1 && svals[r] - svals[r + 1] < TAU) m = true;
                if (m) mask |= 1 << r;
            }
            smask = mask;
        }
        __syncthreads();
    } else {
        // fallback: block-wide full scan of logits; everything recomputed
        __shared__ float sv[512];
        __shared__ int   si[512];
        const float* lr = out + (size_t)row * N_DIM;
        float v[CAND];
        int   id[CAND];
#pragma unroll
        for (int j = 0; j < CAND; j++) { v[j] = NEG_INF; id[j] = 0x7fffffff; }
        for (int c = t; c < N_DIM; c += 512) {
            float val = (c == yr) ? NEG_INF : lr[c];
            if (val > v[CAND - 1]) {
                v[CAND - 1] = val;
                id[CAND - 1] = c;
#pragma unroll
                for (int j = CAND - 1; j > 0; --j) {
                    if (v[j] > v[j - 1]) {
                        float tv = v[j]; v[j] = v[j - 1]; v[j - 1] = tv;
                        int ti = id[j]; id[j] = id[j - 1]; id[j - 1] = ti;
                    }
                }
            }
        }
        int ptr = 0;
        for (int r = 0; r < CAND; ++r) {
            float myv = (ptr < CAND) ? v[ptr] : NEG_INF;
            int   myi = (ptr < CAND) ? id[ptr] : 0x7fffffff;
            sv[t] = myv;
            si[t] = myi;
            __syncthreads();
            for (int s = 256; s > 0; s >>= 1) {
                if (t < s) {
                    float ov = sv[t + s];
                    int   oi = si[t + s];
                    if (ov > sv[t] || (ov == sv[t] && oi < si[t])) {
                        sv[t] = ov; si[t] = oi;
                    }
                }
                __syncthreads();
            }
            if (ptr < CAND && sv[0] == myv && si[0] == myi) ptr++;
            if (t == 0) { svals[r] = sv[0] * INV_SCALE; scols[r] = si[0]; }
            __syncthreads();
        }
        if (t == 0) smask = (1 << CAND) - 1;   // recompute everything
        __syncthreads();
    }

    // ---- DS exact recompute of MARKED candidates only (warp per cand) ----
    if (smask & (1 << warp)) {
        const int c = scols[warp];
        DS dot = {0.f, 0.f}, wss = {0.f, 0.f}, xss = {0.f, 0.f};
        const float* xr = x + (size_t)row * K_DIM;
#pragma unroll 4
        for (int i = lane; i < K_DIM; i += 32) {
            float xi = xr[i];
            float wi = W[(size_t)i * N_DIM + c];
            ds_fma(dot, xi, wi);
            ds_fma(wss, wi, wi);
            ds_fma(xss, xi, xi);
        }
        ds_reduce(dot);
        ds_reduce(wss);
        ds_reduce(xss);
        if (lane == 0) {
            double dd = (double)dot.hi + (double)dot.lo;
            double dw = (double)wss.hi + (double)wss.lo;
            double dx = (double)xss.hi + (double)xss.lo;
            double xn = sqrt(dx); if (xn < (double)EPSN) xn = (double)EPSN;
            double wn = sqrt(dw); if (wn < (double)EPSN) wn = (double)EPSN;
            float f = (float)(dd / (xn * wn));
            f = fminf(1.f, fmaxf(-1.f, f));
            svals[warp] = f;
        }
    }
    __syncthreads();

    // ---- final rank of the 16 (desc value, asc index ties) -> top-10 ----
    if (t == 0) {
        bool used[CAND];
#pragma unroll
        for (int j = 0; j < CAND; j++) used[j] = false;
        for (int r = 0; r < NC; ++r) {
            int   bj = -1;
            float bv = NEG_INF;
            int   bi = 0x7fffffff;
            for (int j = 0; j < CAND; ++j) {
                if (used[j]) continue;
                if (svals[j] > bv || (svals[j] == bv && scols[j] < bi)) {
                    bv = svals[j]; bi = scols[j]; bj = j;
                }
            }
            used[bj] = true;
            out[HARD_OFF + (size_t)row * NC + r] = (float)bi;
        }
    }
}

// ---------------- launch ----------------
extern "C" void kernel_launch(void* const* d_in, const int* in_sizes, int n_in,
                              void* d_out, int out_size) {
    const float* x   = (const float*)d_in[0];
    const float* W   = (const float*)d_in[1];
    const int*   y32 = (const int*)d_in[2];
    float* out = (float*)d_out;

    cudaFuncSetAttribute(arcface_gemm_kernel,
                         cudaFuncAttributeMaxDynamicSharedMemorySize, SMEM_TOTAL);

    ydecode_kernel<<<1, 512>>>(y32);
    xnorm_kernel<<<64, 256>>>(x);
    dim3 grid(4, (N_DIM + 127) / 128);   // M fastest -> W L2 reuse
    arcface_gemm_kernel<<<grid, 256, SMEM_TOTAL>>>(W, out);
    refine_kernel<<<M_DIM, 512>>>(x, W, out);
}

// round 12
// speedup vs baseline: 1.0859x; 1.0859x over previous
#include <cuda_runtime.h>
#include <cuda_fp16.h>
#include <cstdint>

// ---------------- problem constants ----------------
#define M_DIM 512
#define K_DIM 512
#define N_DIM 100000
#define NC    10
#define CAND  16
#define CAP   512
#define THR   0.125f
#define TAU   3e-4f
#define SCALE 64.0f
#define INV_SCALE 0.015625f
#define COS_M  0.87758256189037276f
#define SIN_M  0.47942553860420301f
#define SINM_M 0.23971276930210150f
#define EPSN  1e-12f
#define NEG_INF (-3.402823466e38f)

#define LOGITS_SZ ((size_t)M_DIM * N_DIM)
#define INTRA_OFF LOGITS_SZ
#define HARD_OFF  (LOGITS_SZ + M_DIM)

// ---------------- device scratch ----------------
__device__ __half g_xh[M_DIM * K_DIM];
__device__ __half g_wh[(size_t)K_DIM * N_DIM + 128];   // fp16 W (+pad)
__device__ float  g_colinv[N_DIM + 512];               // 1/||W_col|| (+pad)
__device__ int    g_y[M_DIM];
__device__ int    g_cnt[M_DIM];
__device__ float  g_cval[M_DIM * CAP];
__device__ int    g_ccol[M_DIM * CAP];

// ---------------- PTX helpers ----------------
__device__ __forceinline__ uint32_t smem_u32(const void* p) {
    uint32_t a;
    asm("{ .reg .u64 t; cvta.to.shared.u64 t, %1; cvt.u32.u64 %0, t; }" : "=r"(a) : "l"(p));
    return a;
}
__device__ __forceinline__ void cpa16(uint32_t s, const void* g) {
    asm volatile("cp.async.cg.shared.global [%0], [%1], 16;" :: "r"(s), "l"(g));
}
#define CP_COMMIT() asm volatile("cp.async.commit_group;" ::: "memory")
#define CP_WAIT1()  asm volatile("cp.async.wait_group 1;" ::: "memory")

__device__ __forceinline__ void ldsm4(uint32_t* r, uint32_t a) {
    asm volatile("ldmatrix.sync.aligned.m8n8.x4.shared.b16 {%0,%1,%2,%3}, [%4];"
        : "=r"(r[0]), "=r"(r[1]), "=r"(r[2]), "=r"(r[3]) : "r"(a));
}
__device__ __forceinline__ void ldsm4t(uint32_t* r, uint32_t a) {
    asm volatile("ldmatrix.sync.aligned.m8n8.x4.trans.shared.b16 {%0,%1,%2,%3}, [%4];"
        : "=r"(r[0]), "=r"(r[1]), "=r"(r[2]), "=r"(r[3]) : "r"(a));
}
__device__ __forceinline__ void mma16816(float* c, const uint32_t* a, const uint32_t* b) {
    asm volatile("mma.sync.aligned.m16n8k16.row.col.f32.f16.f16.f32 "
        "{%0,%1,%2,%3}, {%4,%5,%6,%7}, {%8,%9}, {%0,%1,%2,%3};"
        : "+f"(c[0]), "+f"(c[1]), "+f"(c[2]), "+f"(c[3])
        : "r"(a[0]), "r"(a[1]), "r"(a[2]), "r"(a[3]), "r"(b[0]), "r"(b[1]));
}

// ---- double-single (compensated fp32) accumulation ----
struct DS { float hi, lo; };
__device__ __forceinline__ void ds_add(DS& a, float p) {
    float s = a.hi + p;
    float v = s - a.hi;
    float e = (a.hi - (s - v)) + (p - v);
    a.hi = s;
    a.lo += e;
}
__device__ __forceinline__ void ds_fma(DS& a, float x, float w) {
    float p  = x * w;
    float pe = fmaf(x, w, -p);
    ds_add(a, p);
    a.lo += pe;
}
__device__ __forceinline__ void ds_reduce(DS& a) {
#pragma unroll
    for (int o = 16; o; o >>= 1) {
        float oh = __shfl_xor_sync(0xffffffffu, a.hi, o);
        float ol = __shfl_xor_sync(0xffffffffu, a.lo, o);
        float s = a.hi + oh;
        float v = s - a.hi;
        float e = (a.hi - (s - v)) + (oh - v);
        a.hi = s;
        a.lo += ol + e;
    }
}

// ---------------- kernel 0: decode y + zero counters + pads ----------
__global__ void ydecode_kernel(const int* __restrict__ y32) {
    __shared__ int zeros;
    int t = threadIdx.x;
    if (t == 0) zeros = 0;
    __syncthreads();
    if (t < 256) {
        if (y32[2 * t + 1] == 0) atomicAdd(&zeros, 1);
    }
    __syncthreads();
    bool is64 = (zeros > 8);
    g_y[t] = is64 ? y32[2 * t] : y32[t];
    g_cnt[t] = 0;
    if (t < 128) g_wh[(size_t)K_DIM * N_DIM + t] = __float2half(0.f);
    g_colinv[N_DIM + t] = 0.f;      // 512 pad entries
}

// ---------------- kernel 1: row-normalize x -> fp16 ----------------
__global__ void xnorm_kernel(const float* __restrict__ x) {
    int gw   = (blockIdx.x * blockDim.x + threadIdx.x) >> 5;
    int lane = threadIdx.x & 31;
    if (gw >= M_DIM) return;
    const float* xr = x + (size_t)gw * K_DIM;
    float v[16];
    float s = 0.f;
#pragma unroll
    for (int i = 0; i < 16; i++) {
        v[i] = xr[lane + 32 * i];
        s = fmaf(v[i], v[i], s);
    }
#pragma unroll
    for (int o = 16; o; o >>= 1) s += __shfl_xor_sync(0xffffffffu, s, o);
    float inv = 1.0f / fmaxf(sqrtf(s), EPSN);
#pragma unroll
    for (int i = 0; i < 16; i++)
        g_xh[(size_t)gw * K_DIM + lane + 32 * i] = __float2half(v[i] * inv);
}

// ---------------- kernel 2: W fp32 -> fp16 + column norms ----------------
__global__ void wconv_kernel(const float* __restrict__ W) {
    const int n0 = blockIdx.x * 128;
    const int t  = threadIdx.x;
    const int tn = t & 127, tk = t >> 7;
    const int n  = n0 + tn;
    float s = 0.f;
    if (n < N_DIM) {
#pragma unroll 8
        for (int k = tk; k < K_DIM; k += 2) {
            float v = W[(size_t)k * N_DIM + n];
            s = fmaf(v, v, s);
            g_wh[(size_t)k * N_DIM + n] = __float2half(v);
        }
    }
    __shared__ float sh[256];
    sh[t] = s;
    __syncthreads();
    if (t < 128 && n0 + t < N_DIM) {
        float tot = sh[t] + sh[t + 128];
        g_colinv[n0 + t] = 1.0f / fmaxf(sqrtf(tot), EPSN);
    }
}

// ---------------- kernel 3: fp16 mma.sync GEMM, CTA 128x256, warp 64x64 ----
// 8 warps (2m x 4n), BK=64, 2-stage double buffer, 1 CTA/SM.
#define STAGE_STRIDE 49152          // A 16KB + B 32KB per stage
#define SMEM_TOTAL   (2 * STAGE_STRIDE)

__global__ __launch_bounds__(256, 1)
void arcface_gemm_kernel(float* __restrict__ out) {
    extern __shared__ char smem[];
    const uint32_t sb = smem_u32(smem);
    const int tid  = threadIdx.x;
    const int lane = tid & 31;
    const int w    = tid >> 5;
    const int wm   = w >> 2;              // 0..1
    const int wn   = w & 3;               // 0..3
    const int m0   = blockIdx.x * 128;
    const int n0   = blockIdx.y * 256;
    const bool fullt = (n0 + 256 <= N_DIM);

    float acc[4][8][4];
#pragma unroll
    for (int a = 0; a < 4; a++)
#pragma unroll
        for (int b = 0; b < 8; b++)
#pragma unroll
            for (int c = 0; c < 4; c++) acc[a][b][c] = 0.f;

    auto Aaddr = [&](int s, int m, int c) -> uint32_t {
        return sb + s * STAGE_STRIDE + m * 128 + (((c ^ (m & 7)) & 7) << 4);
    };
    auto Baddr = [&](int s, int k, int c) -> uint32_t {
        return sb + s * STAGE_STRIDE + 16384 + k * 512 + (((c ^ (k & 7)) & 31) << 4);
    };

    auto stage = [&](int s, int kc) {
        const int k0 = kc * 64;
#pragma unroll
        for (int j = 0; j < 4; j++) {              // A: 128m x 8 chunks
            int l = tid + j * 256;
            int m = l >> 3, c = l & 7;
            cpa16(Aaddr(s, m, c), g_xh + (size_t)(m0 + m) * K_DIM + k0 + c * 8);
        }
#pragma unroll
        for (int j = 0; j < 8; j++) {              // B: 64k x 32 chunks
            int l = tid + j * 256;
            int k = l >> 5, c = l & 31;
            cpa16(Baddr(s, k, c), g_wh + (size_t)(k0 + k) * N_DIM + n0 + c * 8);
        }
    };

    const int g  = lane >> 3;
    const int l8 = lane & 7;

    auto compute = [&](int s) {
#pragma unroll
        for (int kk = 0; kk < 4; kk++) {
            uint32_t af[4][4];
#pragma unroll
            for (int mi = 0; mi < 4; mi++) {
                int ml = wm * 64 + mi * 16 + (g & 1) * 8 + l8;
                int c0 = kk * 2 + (g >> 1);
                ldsm4(af[mi], Aaddr(s, ml, c0));
            }
            uint32_t bf[4][4];
#pragma unroll
            for (int np = 0; np < 4; np++) {
                int kl = kk * 16 + (g & 1) * 8 + l8;
                int cn = wn * 8 + np * 2 + (g >> 1);
                ldsm4t(bf[np], Baddr(s, kl, cn));
            }
#pragma unroll
            for (int mi = 0; mi < 4; mi++)
#pragma unroll
                for (int ni = 0; ni < 8; ni++)
                    mma16816(acc[mi][ni], af[mi], &bf[ni >> 1][(ni & 1) * 2]);
        }
    };

    stage(0, 0); CP_COMMIT();
    stage(1, 1); CP_COMMIT();
#pragma unroll 1
    for (int kc = 0; kc < 8; kc++) {
        CP_WAIT1();
        __syncthreads();
        compute(kc & 1);
        __syncthreads();
        if (kc + 2 < 8) stage(kc & 1, kc + 2);
        CP_COMMIT();
    }

    // ---------------- epilogue ----------------
#pragma unroll
    for (int mi = 0; mi < 4; mi++) {
        const int rbase = m0 + wm * 64 + mi * 16 + (lane >> 2);
#pragma unroll
        for (int h = 0; h < 2; h++) {
            const int row = rbase + h * 8;
            const int yr  = g_y[row];
            float* orow = out + (size_t)row * N_DIM;
#pragma unroll
            for (int ni = 0; ni < 8; ni++) {
                const int cb = n0 + wn * 64 + ni * 8 + (lane & 3) * 2;
                float lg[2];
#pragma unroll
                for (int e = 0; e < 2; e++) {
                    const int col = cb + e;
                    float c = acc[mi][ni][h * 2 + e] * __ldg(&g_colinv[col]);
                    c = fminf(1.f, fmaxf(-1.f, c));
                    float l = SCALE * c;
                    if (col == yr) {
                        float mg;
                        if (c > -COS_M)
                            mg = c * COS_M - sqrtf(fmaxf(0.f, 1.f - c * c)) * SIN_M;
                        else
                            mg = c - SINM_M;
                        l = SCALE * mg;
                        out[INTRA_OFF + row] = c;
                    } else if (c > THR && col < N_DIM) {
                        int slot = atomicAdd(&g_cnt[row], 1);
                        if (slot < CAP) {
                            g_cval[row * CAP + slot] = c;
                            g_ccol[row * CAP + slot] = col;
                        }
                    }
                    lg[e] = l;
                }
                if (fullt) {
                    *reinterpret_cast<float2*>(orow + cb) = make_float2(lg[0], lg[1]);
                } else {
                    if (cb     < N_DIM) orow[cb]     = lg[0];
                    if (cb + 1 < N_DIM) orow[cb + 1] = lg[1];
                }
            }
        }
    }
}

// ---------------- kernel 4: select + SELECTIVE exact refine --------
__global__ void refine_kernel(const float* __restrict__ x,
                              const float* __restrict__ W,
                              float* __restrict__ out) {
    const int row  = blockIdx.x;
    const int t    = threadIdx.x;
    const int warp = t >> 5;
    const int lane = t & 31;
    const int yr   = g_y[row];

    __shared__ float svals[CAND];
    __shared__ int   scols[CAND];
    __shared__ int   smask;
    const int cnt = g_cnt[row];

    if (cnt >= CAND && cnt <= CAP) {
        if (warp == 0) {
            float v[CAND];
            int   id[CAND];
#pragma unroll
            for (int j = 0; j < CAND; j++) { v[j] = NEG_INF; id[j] = 0x7fffffff; }
            for (int i = lane; i < cnt; i += 32) {
                float val = g_cval[row * CAP + i];
                int   col = g_ccol[row * CAP + i];
                if (val > v[CAND - 1]) {
                    v[CAND - 1] = val;
                    id[CAND - 1] = col;
#pragma unroll
                    for (int j = CAND - 1; j > 0; --j) {
                        if (v[j] > v[j - 1]) {
                            float tv = v[j]; v[j] = v[j - 1]; v[j - 1] = tv;
                            int ti = id[j]; id[j] = id[j - 1]; id[j - 1] = ti;
                        }
                    }
                }
            }
            int ptr = 0;
            for (int r = 0; r < CAND; ++r) {
                float myv = (ptr < CAND) ? v[ptr] : NEG_INF;
                int   myi = (ptr < CAND) ? id[ptr] : 0x7fffffff;
                float bv = myv;
                int   bi = myi;
#pragma unroll
                for (int o = 16; o; o >>= 1) {
                    float ov = __shfl_xor_sync(0xffffffffu, bv, o);
                    int   oi = __shfl_xor_sync(0xffffffffu, bi, o);
                    if (ov > bv || (ov == bv && oi < bi)) { bv = ov; bi = oi; }
                }
                if (ptr < CAND && bi == myi) ptr++;
                if (lane == 0) { svals[r] = bv; scols[r] = bi; }
            }
        }
        __syncthreads();
        if (t == 0) {
            int mask = 0;
            for (int r = 0; r < CAND; ++r) {
                bool m = false;
                if (r > 0        && svals[r - 1] - svals[r] < TAU) m = true;
                if (r < CAND - 1 && svals[r] - svals[r + 1] < TAU) m = true;
                if (m) mask |= 1 << r;
            }
            smask = mask;
        }
        __syncthreads();
    } else {
        __shared__ float sv[512];
        __shared__ int   si[512];
        const float* lr = out + (size_t)row * N_DIM;
        float v[CAND];
        int   id[CAND];
#pragma unroll
        for (int j = 0; j < CAND; j++) { v[j] = NEG_INF; id[j] = 0x7fffffff; }
        for (int c = t; c < N_DIM; c += 512) {
            float val = (c == yr) ? NEG_INF : lr[c];
            if (val > v[CAND - 1]) {
                v[CAND - 1] = val;
                id[CAND - 1] = c;
#pragma unroll
                for (int j = CAND - 1; j > 0; --j) {
                    if (v[j] > v[j - 1]) {
                        float tv = v[j]; v[j] = v[j - 1]; v[j - 1] = tv;
                        int ti = id[j]; id[j] = id[j - 1]; id[j - 1] = ti;
                    }
                }
            }
        }
        int ptr = 0;
        for (int r = 0; r < CAND; ++r) {
            float myv = (ptr < CAND) ? v[ptr] : NEG_INF;
            int   myi = (ptr < CAND) ? id[ptr] : 0x7fffffff;
            sv[t] = myv;
            si[t] = myi;
            __syncthreads();
            for (int s = 256; s > 0; s >>= 1) {
                if (t < s) {
                    float ov = sv[t + s];
                    int   oi = si[t + s];
                    if (ov > sv[t] || (ov == sv[t] && oi < si[t])) {
                        sv[t] = ov; si[t] = oi;
                    }
                }
                __syncthreads();
            }
            if (ptr < CAND && sv[0] == myv && si[0] == myi) ptr++;
            if (t == 0) { svals[r] = sv[0] * INV_SCALE; scols[r] = si[0]; }
            __syncthreads();
        }
        if (t == 0) smask = (1 << CAND) - 1;
        __syncthreads();
    }

    // ---- DS exact recompute of MARKED candidates (batched loads, MLP=16) ----
    if (smask & (1 << warp)) {
        const int c = scols[warp];
        const float* xr = x + (size_t)row * K_DIM;
        float xv[16], wv[16];
#pragma unroll
        for (int j = 0; j < 16; j++) {
            int i = lane + 32 * j;
            xv[j] = xr[i];
            wv[j] = W[(size_t)i * N_DIM + c];
        }
        DS dot = {0.f, 0.f}, wss = {0.f, 0.f}, xss = {0.f, 0.f};
#pragma unroll
        for (int j = 0; j < 16; j++) {
            ds_fma(dot, xv[j], wv[j]);
            ds_fma(wss, wv[j], wv[j]);
            ds_fma(xss, xv[j], xv[j]);
        }
        ds_reduce(dot);
        ds_reduce(wss);
        ds_reduce(xss);
        if (lane == 0) {
            double dd = (double)dot.hi + (double)dot.lo;
            double dw = (double)wss.hi + (double)wss.lo;
            double dx = (double)xss.hi + (double)xss.lo;
            double xn = sqrt(dx); if (xn < (double)EPSN) xn = (double)EPSN;
            double wn = sqrt(dw); if (wn < (double)EPSN) wn = (double)EPSN;
            float f = (float)(dd / (xn * wn));
            f = fminf(1.f, fmaxf(-1.f, f));
            svals[warp] = f;
        }
    }
    __syncthreads();

    if (t == 0) {
        bool used[CAND];
#pragma unroll
        for (int j = 0; j < CAND; j++) used[j] = false;
        for (int r = 0; r < NC; ++r) {
            int   bj = -1;
            float bv = NEG_INF;
            int   bi = 0x7fffffff;
            for (int j = 0; j < CAND; ++j) {
                if (used[j]) continue;
                if (svals[j] > bv || (svals[j] == bv && scols[j] < bi)) {
                    bv = svals[j]; bi = scols[j]; bj = j;
                }
            }
            used[bj] = true;
            out[HARD_OFF + (size_t)row * NC + r] = (float)bi;
        }
    }
}

// ---------------- launch ----------------
extern "C" void kernel_launch(void* const* d_in, const int* in_sizes, int n_in,
                              void* d_out, int out_size) {
    const float* x   = (const float*)d_in[0];
    const float* W   = (const float*)d_in[1];
    const int*   y32 = (const int*)d_in[2];
    float* out = (float*)d_out;

    cudaFuncSetAttribute(arcface_gemm_kernel,
                         cudaFuncAttributeMaxDynamicSharedMemorySize, SMEM_TOTAL);

    ydecode_kernel<<<1, 512>>>(y32);
    xnorm_kernel<<<64, 256>>>(x);
    wconv_kernel<<<(N_DIM + 127) / 128, 256>>>(W);
    dim3 grid(4, (N_DIM + 255) / 256);   // M fastest -> W L2 reuse
    arcface_gemm_kernel<<<grid, 256, SMEM_TOTAL>>>(out);
    refine_kernel<<<M_DIM, 512>>>(x, W, out);
}

// round 16
// speedup vs baseline: 1.5007x; 1.3820x over previous
#include <cuda_runtime.h>
#include <cuda_fp16.h>
#include <cstdint>

// ---------------- problem constants ----------------
#define M_DIM 512
#define K_DIM 512
#define N_DIM 100000
#define NC    10
#define CAND  16
#define CAP   512
#define THR   0.125f
#define TAU   3e-4f
#define SCALE 64.0f
#define INV_SCALE 0.015625f
#define COS_M  0.87758256189037276f
#define SIN_M  0.47942553860420301f
#define SINM_M 0.23971276930210150f
#define EPSN  1e-12f
#define NEG_INF (-3.402823466e38f)

#define LOGITS_SZ ((size_t)M_DIM * N_DIM)
#define INTRA_OFF LOGITS_SZ
#define HARD_OFF  (LOGITS_SZ + M_DIM)

// ---------------- device scratch ----------------
__device__ __half g_xh[M_DIM * K_DIM];
__device__ __half g_wh[(size_t)K_DIM * N_DIM + 128];   // fp16 W (+pad)
__device__ float  g_colinv[N_DIM + 512];               // 1/||W_col|| (+pad)
__device__ int    g_y[M_DIM];
__device__ int    g_cnt[M_DIM];
__device__ float  g_cval[M_DIM * CAP];
__device__ int    g_ccol[M_DIM * CAP];

// ---------------- PTX helpers ----------------
__device__ __forceinline__ uint32_t smem_u32(const void* p) {
    uint32_t a;
    asm("{ .reg .u64 t; cvta.to.shared.u64 t, %1; cvt.u32.u64 %0, t; }" : "=r"(a) : "l"(p));
    return a;
}
__device__ __forceinline__ void cpa16(uint32_t s, const void* g) {
    asm volatile("cp.async.cg.shared.global [%0], [%1], 16;" :: "r"(s), "l"(g));
}
#define CP_COMMIT() asm volatile("cp.async.commit_group;" ::: "memory")
#define CP_WAIT1()  asm volatile("cp.async.wait_group 1;" ::: "memory")

__device__ __forceinline__ void ldsm4(uint32_t* r, uint32_t a) {
    asm volatile("ldmatrix.sync.aligned.m8n8.x4.shared.b16 {%0,%1,%2,%3}, [%4];"
        : "=r"(r[0]), "=r"(r[1]), "=r"(r[2]), "=r"(r[3]) : "r"(a));
}
__device__ __forceinline__ void ldsm4t(uint32_t* r, uint32_t a) {
    asm volatile("ldmatrix.sync.aligned.m8n8.x4.trans.shared.b16 {%0,%1,%2,%3}, [%4];"
        : "=r"(r[0]), "=r"(r[1]), "=r"(r[2]), "=r"(r[3]) : "r"(a));
}
__device__ __forceinline__ void mma16816(float* c, const uint32_t* a, const uint32_t* b) {
    asm volatile("mma.sync.aligned.m16n8k16.row.col.f32.f16.f16.f32 "
        "{%0,%1,%2,%3}, {%4,%5,%6,%7}, {%8,%9}, {%0,%1,%2,%3};"
        : "+f"(c[0]), "+f"(c[1]), "+f"(c[2]), "+f"(c[3])
        : "r"(a[0]), "r"(a[1]), "r"(a[2]), "r"(a[3]), "r"(b[0]), "r"(b[1]));
}

// ---- double-single (compensated fp32) accumulation ----
struct DS { float hi, lo; };
__device__ __forceinline__ void ds_add(DS& a, float p) {
    float s = a.hi + p;
    float v = s - a.hi;
    float e = (a.hi - (s - v)) + (p - v);
    a.hi = s;
    a.lo += e;
}
__device__ __forceinline__ void ds_fma(DS& a, float x, float w) {
    float p  = x * w;
    float pe = fmaf(x, w, -p);
    ds_add(a, p);
    a.lo += pe;
}
__device__ __forceinline__ void ds_reduce(DS& a) {
#pragma unroll
    for (int o = 16; o; o >>= 1) {
        float oh = __shfl_xor_sync(0xffffffffu, a.hi, o);
        float ol = __shfl_xor_sync(0xffffffffu, a.lo, o);
        float s = a.hi + oh;
        float v = s - a.hi;
        float e = (a.hi - (s - v)) + (oh - v);
        a.hi = s;
        a.lo += ol + e;
    }
}

// ---------------- kernel 0: decode y + zero counters + pads ----------
__global__ void ydecode_kernel(const int* __restrict__ y32) {
    __shared__ int zeros;
    int t = threadIdx.x;
    if (t == 0) zeros = 0;
    __syncthreads();
    if (t < 256) {
        if (y32[2 * t + 1] == 0) atomicAdd(&zeros, 1);
    }
    __syncthreads();
    bool is64 = (zeros > 8);
    g_y[t] = is64 ? y32[2 * t] : y32[t];
    g_cnt[t] = 0;
    if (t < 128) g_wh[(size_t)K_DIM * N_DIM + t] = __float2half(0.f);
    g_colinv[N_DIM + t] = 0.f;
}

// ---------------- kernel 1: row-normalize x -> fp16 ----------------
__global__ void xnorm_kernel(const float* __restrict__ x) {
    int gw   = (blockIdx.x * blockDim.x + threadIdx.x) >> 5;
    int lane = threadIdx.x & 31;
    if (gw >= M_DIM) return;
    const float* xr = x + (size_t)gw * K_DIM;
    float v[16];
    float s = 0.f;
#pragma unroll
    for (int i = 0; i < 16; i++) {
        v[i] = xr[lane + 32 * i];
        s = fmaf(v[i], v[i], s);
    }
#pragma unroll
    for (int o = 16; o; o >>= 1) s += __shfl_xor_sync(0xffffffffu, s, o);
    float inv = 1.0f / fmaxf(sqrtf(s), EPSN);
#pragma unroll
    for (int i = 0; i < 16; i++)
        g_xh[(size_t)gw * K_DIM + lane + 32 * i] = __float2half(v[i] * inv);
}

// ---------------- kernel 2: W fp32 -> fp16 + column norms ----------------
__global__ void wconv_kernel(const float* __restrict__ W) {
    const int n0 = blockIdx.x * 128;
    const int t  = threadIdx.x;
    const int tn = t & 127, tk = t >> 7;
    const int n  = n0 + tn;
    float s = 0.f;
    if (n < N_DIM) {
#pragma unroll 8
        for (int k = tk; k < K_DIM; k += 2) {
            float v = W[(size_t)k * N_DIM + n];
            s = fmaf(v, v, s);
            g_wh[(size_t)k * N_DIM + n] = __float2half(v);
        }
    }
    __shared__ float sh[256];
    sh[t] = s;
    __syncthreads();
    if (t < 128 && n0 + t < N_DIM) {
        float tot = sh[t] + sh[t + 128];
        g_colinv[n0 + t] = 1.0f / fmaxf(sqrtf(tot), EPSN);
    }
}

// ---------------- kernel 3: fp16 mma.sync GEMM (128x128, 3-stage, 2 CTA/SM) -
#define BK 64
#define STAGE_BYTES 32768
#define SMEM_TOTAL  (3 * STAGE_BYTES)

__global__ __launch_bounds__(256, 2)
void arcface_gemm_kernel(float* __restrict__ out) {
    extern __shared__ char smem[];
    const uint32_t sb = smem_u32(smem);
    const int tid  = threadIdx.x;
    const int lane = tid & 31;
    const int w    = tid >> 5;
    const int wm   = w >> 2;
    const int wn   = w & 3;
    const int m0   = blockIdx.x * 128;
    const int n0   = blockIdx.y * 128;

    float acc[4][4][4];
#pragma unroll
    for (int a = 0; a < 4; a++)
#pragma unroll
        for (int b = 0; b < 4; b++)
#pragma unroll
            for (int c = 0; c < 4; c++) acc[a][b][c] = 0.f;

    auto Aaddr = [&](int s, int m, int c) -> uint32_t {
        return sb + s * STAGE_BYTES + m * 128 + (((c ^ (m & 7)) & 7) << 4);
    };
    auto Baddr = [&](int s, int k, int c) -> uint32_t {
        return sb + s * STAGE_BYTES + 16384 + k * 256 + (((c ^ (k & 7)) & 15) << 4);
    };

    auto stage = [&](int s, int kc) {
        const int k0 = kc * BK;
#pragma unroll
        for (int j = 0; j < 4; j++) {
            int l = tid + j * 256;
            int m = l >> 3, c = l & 7;
            cpa16(Aaddr(s, m, c), g_xh + (size_t)(m0 + m) * K_DIM + k0 + c * 8);
        }
#pragma unroll
        for (int j = 0; j < 4; j++) {
            int l = tid + j * 256;
            int k = l >> 4, c = l & 15;
            cpa16(Baddr(s, k, c), g_wh + (size_t)(k0 + k) * N_DIM + n0 + c * 8);
        }
    };

    const int g  = lane >> 3;
    const int l8 = lane & 7;

    auto compute = [&](int s) {
#pragma unroll
        for (int kk = 0; kk < 4; kk++) {
            uint32_t af[4][4];
#pragma unroll
            for (int mi = 0; mi < 4; mi++) {
                int ml = wm * 64 + mi * 16 + (g & 1) * 8 + l8;
                int c0 = kk * 2 + (g >> 1);
                ldsm4(af[mi], Aaddr(s, ml, c0));
            }
            uint32_t bf[2][4];
#pragma unroll
            for (int np = 0; np < 2; np++) {
                int kl = kk * 16 + (g & 1) * 8 + l8;
                int cn = wn * 4 + np * 2 + (g >> 1);
                ldsm4t(bf[np], Baddr(s, kl, cn));
            }
#pragma unroll
            for (int mi = 0; mi < 4; mi++)
#pragma unroll
                for (int ni = 0; ni < 4; ni++)
                    mma16816(acc[mi][ni], af[mi], &bf[ni >> 1][(ni & 1) * 2]);
        }
    };

    stage(0, 0); CP_COMMIT();
    stage(1, 1); CP_COMMIT();
#pragma unroll 1
    for (int kc = 0; kc < 8; kc++) {
        CP_WAIT1();
        __syncthreads();             // buffer kc%3 visible; buffer (kc+2)%3 retired
        if (kc + 2 < 8) stage((kc + 2) % 3, kc + 2);
        CP_COMMIT();
        compute(kc % 3);
    }

    // ---------------- epilogue ----------------
    const bool fullt = (n0 + 128 <= N_DIM);
#pragma unroll
    for (int mi = 0; mi < 4; mi++) {
        const int rbase = m0 + wm * 64 + mi * 16 + (lane >> 2);
#pragma unroll
        for (int h = 0; h < 2; h++) {
            const int row = rbase + h * 8;
            const int yr  = g_y[row];
            float* orow = out + (size_t)row * N_DIM;
#pragma unroll
            for (int ni = 0; ni < 4; ni++) {
                const int cb = n0 + wn * 32 + ni * 8 + (lane & 3) * 2;
                float lg[2];
#pragma unroll
                for (int e = 0; e < 2; e++) {
                    const int col = cb + e;
                    float c = acc[mi][ni][h * 2 + e] * __ldg(&g_colinv[col]);
                    c = fminf(1.f, fmaxf(-1.f, c));
                    float l = SCALE * c;
                    if (col == yr) {
                        float mg;
                        if (c > -COS_M)
                            mg = c * COS_M - sqrtf(fmaxf(0.f, 1.f - c * c)) * SIN_M;
                        else
                            mg = c - SINM_M;
                        l = SCALE * mg;
                        out[INTRA_OFF + row] = c;
                    } else if (c > THR && col < N_DIM) {
                        int slot = atomicAdd(&g_cnt[row], 1);
                        if (slot < CAP) {
                            g_cval[row * CAP + slot] = c;
                            g_ccol[row * CAP + slot] = col;
                        }
                    }
                    lg[e] = l;
                }
                if (fullt) {
                    *reinterpret_cast<float2*>(orow + cb) = make_float2(lg[0], lg[1]);
                } else {
                    if (cb     < N_DIM) orow[cb]     = lg[0];
                    if (cb + 1 < N_DIM) orow[cb + 1] = lg[1];
                }
            }
        }
    }
}

// ---------------- kernel 4: select + SELECTIVE exact refine --------
__global__ void refine_kernel(const float* __restrict__ x,
                              const float* __restrict__ W,
                              float* __restrict__ out) {
    const int row  = blockIdx.x;
    const int t    = threadIdx.x;
    const int warp = t >> 5;
    const int lane = t & 31;
    const int yr   = g_y[row];

    __shared__ float svals[CAND];
    __shared__ int   scols[CAND];
    __shared__ int   smask;
    const int cnt = g_cnt[row];

    if (cnt >= CAND && cnt <= CAP) {
        if (warp == 0) {
            float v[CAND];
            int   id[CAND];
#pragma unroll
            for (int j = 0; j < CAND; j++) { v[j] = NEG_INF; id[j] = 0x7fffffff; }
            for (int i = lane; i < cnt; i += 32) {
                float val = g_cval[row * CAP + i];
                int   col = g_ccol[row * CAP + i];
                if (val > v[CAND - 1]) {
                    v[CAND - 1] = val;
                    id[CAND - 1] = col;
#pragma unroll
                    for (int j = CAND - 1; j > 0; --j) {
                        if (v[j] > v[j - 1]) {
                            float tv = v[j]; v[j] = v[j - 1]; v[j - 1] = tv;
                            int ti = id[j]; id[j] = id[j - 1]; id[j - 1] = ti;
                        }
                    }
                }
            }
            int ptr = 0;
            for (int r = 0; r < CAND; ++r) {
                float myv = (ptr < CAND) ? v[ptr] : NEG_INF;
                int   myi = (ptr < CAND) ? id[ptr] : 0x7fffffff;
                float bv = myv;
                int   bi = myi;
#pragma unroll
                for (int o = 16; o; o >>= 1) {
                    float ov = __shfl_xor_sync(0xffffffffu, bv, o);
                    int   oi = __shfl_xor_sync(0xffffffffu, bi, o);
                    if (ov > bv || (ov == bv && oi < bi)) { bv = ov; bi = oi; }
                }
                if (ptr < CAND && bi == myi) ptr++;
                if (lane == 0) { svals[r] = bv; scols[r] = bi; }
            }
        }
        __syncthreads();
        if (t == 0) {
            int mask = 0;
            for (int r = 0; r < CAND; ++r) {
                bool m = false;
                if (r > 0        && svals[r - 1] - svals[r] < TAU) m = true;
                if (r < CAND - 1 && svals[r] - svals[r + 1] < TAU) m = true;
                if (m) mask |= 1 << r;
            }
            smask = mask;
        }
        __syncthreads();
    } else {
        __shared__ float sv[512];
        __shared__ int   si[512];
        const float* lr = out + (size_t)row * N_DIM;
        float v[CAND];
        int   id[CAND];
#pragma unroll
        for (int j = 0; j < CAND; j++) { v[j] = NEG_INF; id[j] = 0x7fffffff; }
        for (int c = t; c < N_DIM; c += 512) {
            float val = (c == yr) ? NEG_INF : lr[c];
            if (val > v[CAND - 1]) {
                v[CAND - 1] = val;
                id[CAND - 1] = c;
#pragma unroll
                for (int j = CAND - 1; j > 0; --j) {
                    if (v[j] > v[j - 1]) {
                        float tv = v[j]; v[j] = v[j - 1]; v[j - 1] = tv;
                        int ti = id[j]; id[j] = id[j - 1]; id[j - 1] = ti;
                    }
                }
            }
        }
        int ptr = 0;
        for (int r = 0; r < CAND; ++r) {
            float myv = (ptr < CAND) ? v[ptr] : NEG_INF;
            int   myi = (ptr < CAND) ? id[ptr] : 0x7fffffff;
            sv[t] = myv;
            si[t] = myi;
            __syncthreads();
            for (int s = 256; s > 0; s >>= 1) {
                if (t < s) {
                    float ov = sv[t + s];
                    int   oi = si[t + s];
                    if (ov > sv[t] || (ov == sv[t] && oi < si[t])) {
                        sv[t] = ov; si[t] = oi;
                    }
                }
                __syncthreads();
            }
            if (ptr < CAND && sv[0] == myv && si[0] == myi) ptr++;
            if (t == 0) { svals[r] = sv[0] * INV_SCALE; scols[r] = si[0]; }
            __syncthreads();
        }
        if (t == 0) smask = (1 << CAND) - 1;
        __syncthreads();
    }

    // ---- DS exact recompute of MARKED candidates (batched loads, MLP=16) ----
    if (smask & (1 << warp)) {
        const int c = scols[warp];
        const float* xr = x + (size_t)row * K_DIM;
        float xv[16], wv[16];
#pragma unroll
        for (int j = 0; j < 16; j++) {
            int i = lane + 32 * j;
            xv[j] = xr[i];
            wv[j] = W[(size_t)i * N_DIM + c];
        }
        DS dot = {0.f, 0.f}, wss = {0.f, 0.f}, xss = {0.f, 0.f};
#pragma unroll
        for (int j = 0; j < 16; j++) {
            ds_fma(dot, xv[j], wv[j]);
            ds_fma(wss, wv[j], wv[j]);
            ds_fma(xss, xv[j], xv[j]);
        }
        ds_reduce(dot);
        ds_reduce(wss);
        ds_reduce(xss);
        if (lane == 0) {
            double dd = (double)dot.hi + (double)dot.lo;
            double dw = (double)wss.hi + (double)wss.lo;
            double dx = (double)xss.hi + (double)xss.lo;
            double xn = sqrt(dx); if (xn < (double)EPSN) xn = (double)EPSN;
            double wn = sqrt(dw); if (wn < (double)EPSN) wn = (double)EPSN;
            float f = (float)(dd / (xn * wn));
            f = fminf(1.f, fmaxf(-1.f, f));
            svals[warp] = f;
        }
    }
    __syncthreads();

    if (t == 0) {
        bool used[CAND];
#pragma unroll
        for (int j = 0; j < CAND; j++) used[j] = false;
        for (int r = 0; r < NC; ++r) {
            int   bj = -1;
            float bv = NEG_INF;
            int   bi = 0x7fffffff;
            for (int j = 0; j < CAND; ++j) {
                if (used[j]) continue;
                if (svals[j] > bv || (svals[j] == bv && scols[j] < bi)) {
                    bv = svals[j]; bi = scols[j]; bj = j;
                }
            }
            used[bj] = true;
            out[HARD_OFF + (size_t)row * NC + r] = (float)bi;
        }
    }
}

// ---------------- launch ----------------
extern "C" void kernel_launch(void* const* d_in, const int* in_sizes, int n_in,
                              void* d_out, int out_size) {
    const float* x   = (const float*)d_in[0];
    const float* W   = (const float*)d_in[1];
    const int*   y32 = (const int*)d_in[2];
    float* out = (float*)d_out;

    cudaFuncSetAttribute(arcface_gemm_kernel,
                         cudaFuncAttributeMaxDynamicSharedMemorySize, SMEM_TOTAL);

    ydecode_kernel<<<1, 512>>>(y32);
    xnorm_kernel<<<64, 256>>>(x);
    wconv_kernel<<<(N_DIM + 127) / 128, 256>>>(W);
    dim3 grid(4, (N_DIM + 127) / 128);   // M fastest -> W L2 reuse
    arcface_gemm_kernel<<<grid, 256, SMEM_TOTAL>>>(out);
    refine_kernel<<<M_DIM, 512>>>(x, W, out);
}